// round 11
// baseline (speedup 1.0000x reference)
#include <cuda_runtime.h>
#include <cuda_bf16.h>
#include <cstdint>

// ---------------- problem constants ----------------
#define BROWS   65536
#define DDIM    1024
#define NCOLS   128      // 120 real columns padded to 128
#define KC      64       // K elems per chunk
#define NCHUNK  (DDIM / KC)   // 16
#define NSTEP   (NCHUNK * 4)  // 64 global k-tile steps
#define TILE_M  128
#define APAD    72       // B smem row pitch (bf16): 144B rows -> conflict-free LDSM
#define OPAD    130      // out-tile row pitch (floats)

#define BBYTES  (NCOLS * APAD * 2)      // 18432 per B buffer
#define SMEM_BYTES (TILE_M * OPAD * 4)  // 66560 (>= 2*BBYTES=36864)

// packed weights: [NCOLS][DDIM] bf16, k-PERMUTED within each 16-block (see kperm)
__device__ __align__(16) __nv_bfloat16 g_Wpack[NCOLS * DDIM];

// stored position p (0..15) -> actual k. Bijective per 16-block.
// A direct-LDG places actual k {4t,4t+1,4t+2,4t+3} at positions {2t,2t+1,2t+8,2t+9};
// packing B with the same map keeps the MMA's positional k-pairing consistent.
__host__ __device__ __forceinline__ int kperm(int p) {
    return (p < 8) ? ((p >> 1) * 4 + (p & 1))
                   : (((p - 8) >> 1) * 4 + 2 + (p & 1));
}

__device__ __forceinline__ uint32_t smem_u32(const void* p) {
    uint32_t a;
    asm("{ .reg .u64 t; cvta.to.shared.u64 t, %1; cvt.u32.u64 %0, t; }" : "=r"(a) : "l"(p));
    return a;
}
#define CP_ASYNC16(dst_u32, src_ptr) \
    asm volatile("cp.async.cg.shared.global [%0], [%1], 16;" :: "r"(dst_u32), "l"(src_ptr) : "memory")
#define CP_COMMIT() asm volatile("cp.async.commit_group;" ::: "memory")
#define CP_WAIT0()  asm volatile("cp.async.wait_group 0;" ::: "memory")
#define LDSM_X4(r0, r1, r2, r3, addr) \
    asm volatile("ldmatrix.sync.aligned.m8n8.x4.shared.b16 {%0,%1,%2,%3}, [%4];" \
                 : "=r"(r0), "=r"(r1), "=r"(r2), "=r"(r3) : "r"(addr))

// ---------------- weight pack kernel (coalesced + k-permuted) ----------------
// grid (12, 4) x 256 thr.  bx<10: expert e=bx;  bx 10,11: gate t=bx-10.
__global__ void pack_weights_kernel(const float* __restrict__ expert_w,
                                    const float* __restrict__ gate_w) {
    __shared__ float s[256][10];
    const int bx = blockIdx.x;
    const int d0 = blockIdx.y * 256;
    const int tid = threadIdx.x;
    const float* src = (bx < 10) ? expert_w + (size_t)bx * DDIM * 10
                                 : gate_w   + (size_t)(bx - 10) * DDIM * 10;
    #pragma unroll
    for (int k = 0; k < 10; ++k) {
        int idx = tid + k * 256;                  // coalesced reads
        s[idx / 10][idx % 10] = src[(size_t)d0 * 10 + idx];
    }
    __syncthreads();
    const int j0 = (bx < 10) ? bx * 10 : 100 + (bx - 10) * 10;
    const int srcLocal = (tid & ~15) | kperm(tid & 15);   // permute within 16-block
    #pragma unroll
    for (int r = 0; r < 10; ++r)                  // coalesced writes
        g_Wpack[(size_t)(j0 + r) * DDIM + d0 + tid] = __float2bfloat16(s[srcLocal][r]);
}

// ---------------- fused MMoE main kernel (128x128 tile, A fragment-direct) ----
extern "C" __global__ void __launch_bounds__(256, 2)
mmoe_main_kernel(const float* __restrict__ x,
                 const float* __restrict__ expert_b,   // [10,10]
                 const float* __restrict__ gate_b,     // [2,10]
                 const float* __restrict__ ctr_w,      // [10]
                 const float* __restrict__ ctr_b,      // [1]
                 const float* __restrict__ cvr_w,      // [10]
                 const float* __restrict__ cvr_b,      // [1]
                 float* __restrict__ out) {            // [2*B] = [ctr | cvr]
    extern __shared__ char smem[];
    const uint32_t smem_base = smem_u32(smem);
    float* outS = reinterpret_cast<float*>(smem);

    const int tid  = threadIdx.x;
    const int wid  = tid >> 5;
    const int lane = tid & 31;
    const int gid  = lane >> 2;   // 0..7
    const int tig  = lane & 3;    // 0..3
    const int warp_m = (wid & 3) * 32;    // 4 warps along M
    const int warp_n = (wid >> 2) * 64;   // 2 warps along N
    const int row0 = blockIdx.x * TILE_M;
    const int wstag = wid & 3;            // per-warp kt phase stagger

    // B ldmatrix per-lane base byte offset (within a B stage buffer)
    const uint32_t bLdsmBase =
        (uint32_t)(warp_n + ((lane >> 4) & 1) * 8 + (lane & 7)) * (APAD * 2)
        + ((lane >> 3) & 1) * 16;

    // B cp.async mapping
    const int brb = tid >> 3;            // rows brb + it*32 (it<4)
    const int c8  = tid & 7;             // col uint4

    // A direct-LDG base: row = row0 + warp_m + gid (+8*rr +16*mt), col = tig*4 (+step)
    const float* aBase = x + (size_t)(row0 + warp_m + gid) * DDIM + tig * 4;

    float acc[2][8][4];
    #pragma unroll
    for (int mt = 0; mt < 2; ++mt)
        #pragma unroll
        for (int nt = 0; nt < 8; ++nt)
            #pragma unroll
            for (int i = 0; i < 4; ++i) acc[mt][nt][i] = 0.0f;

    // A fragment pipeline: fb[step&1][mt][rr], 2 steps of lead
    float4 fb[2][2][2];

    auto stepCol = [&](int g) -> int {     // global column of step g (warp-staggered)
        return (g >> 2) * KC + ((((g & 3) + wstag) & 3) << 4);
    };
    auto ldgA = [&](int g) {               // prefetch step g's A float4s
        if (g < NSTEP) {
            const float* p = aBase + stepCol(g);
            const int s = g & 1;
            fb[s][0][0] = *reinterpret_cast<const float4*>(p);
            fb[s][0][1] = *reinterpret_cast<const float4*>(p + 8  * DDIM);
            fb[s][1][0] = *reinterpret_cast<const float4*>(p + 16 * DDIM);
            fb[s][1][1] = *reinterpret_cast<const float4*>(p + 24 * DDIM);
        }
    };
    auto issue_B = [&](int c) {            // cp.async B chunk c into buffer (c&1)
        const int k0 = c * KC;
        const uint32_t bb = smem_base + (c & 1) * BBYTES;
        #pragma unroll
        for (int it = 0; it < 4; ++it)
            CP_ASYNC16(bb + (uint32_t)((brb + it * 32) * APAD + c8 * 8) * 2,
                       g_Wpack + (size_t)(brb + it * 32) * DDIM + k0 + c8 * 8);
        CP_COMMIT();
    };

    // ---- prologue ----
    issue_B(0);
    ldgA(0);
    ldgA(1);
    CP_WAIT0();

    for (int c = 0; c < NCHUNK; ++c) {
        __syncthreads();                   // B(c) visible; compute(c-1) retired
        if (c + 1 < NCHUNK) issue_B(c + 1);

        const uint32_t bStage = smem_base + (c & 1) * BBYTES;

        #pragma unroll
        for (int j = 0; j < 4; ++j) {
            const int g = c * 4 + j;
            const int s = g & 1;
            const uint32_t kOff = (uint32_t)(((((g & 3) + wstag) & 3)) << 5);

            // build A frags from the prefetched float4s (permuted-k order)
            uint32_t afrag[2][4];
            #pragma unroll
            for (int mt = 0; mt < 2; ++mt) {
                const float4 v0 = fb[s][mt][0];   // row gid
                const float4 v1 = fb[s][mt][1];   // row gid+8
                __nv_bfloat162 h0 = __floats2bfloat162_rn(v0.x, v0.y);
                __nv_bfloat162 h1 = __floats2bfloat162_rn(v1.x, v1.y);
                __nv_bfloat162 h2 = __floats2bfloat162_rn(v0.z, v0.w);
                __nv_bfloat162 h3 = __floats2bfloat162_rn(v1.z, v1.w);
                afrag[mt][0] = *reinterpret_cast<uint32_t*>(&h0);
                afrag[mt][1] = *reinterpret_cast<uint32_t*>(&h1);
                afrag[mt][2] = *reinterpret_cast<uint32_t*>(&h2);
                afrag[mt][3] = *reinterpret_cast<uint32_t*>(&h3);
            }
            ldgA(g + 2);                   // refill freed slot, 2-step lead

            #pragma unroll
            for (int pr = 0; pr < 4; ++pr) {
                uint32_t b0a, b1a, b0b, b1b;
                LDSM_X4(b0a, b1a, b0b, b1b,
                        bStage + bLdsmBase + (uint32_t)(pr * 16 * APAD * 2) + kOff);
                #pragma unroll
                for (int mt = 0; mt < 2; ++mt) {
                    asm volatile(
                        "mma.sync.aligned.m16n8k16.row.col.f32.bf16.bf16.f32 "
                        "{%0,%1,%2,%3}, {%4,%5,%6,%7}, {%8,%9}, {%0,%1,%2,%3};"
                        : "+f"(acc[mt][2 * pr][0]), "+f"(acc[mt][2 * pr][1]),
                          "+f"(acc[mt][2 * pr][2]), "+f"(acc[mt][2 * pr][3])
                        : "r"(afrag[mt][0]), "r"(afrag[mt][1]),
                          "r"(afrag[mt][2]), "r"(afrag[mt][3]),
                          "r"(b0a), "r"(b1a));
                    asm volatile(
                        "mma.sync.aligned.m16n8k16.row.col.f32.bf16.bf16.f32 "
                        "{%0,%1,%2,%3}, {%4,%5,%6,%7}, {%8,%9}, {%0,%1,%2,%3};"
                        : "+f"(acc[mt][2 * pr + 1][0]), "+f"(acc[mt][2 * pr + 1][1]),
                          "+f"(acc[mt][2 * pr + 1][2]), "+f"(acc[mt][2 * pr + 1][3])
                        : "r"(afrag[mt][0]), "r"(afrag[mt][1]),
                          "r"(afrag[mt][2]), "r"(afrag[mt][3]),
                          "r"(b0b), "r"(b1b));
                }
            }
        }
        if (c + 1 < NCHUNK) CP_WAIT0();    // B(c+1) landed (full chunk in flight)
    }
    __syncthreads();   // MMAs done; B buffers dead -> reuse smem as outS

    // --- scatter accumulators to fp32 out tile ---
    #pragma unroll
    for (int mt = 0; mt < 2; ++mt) {
        #pragma unroll
        for (int nt = 0; nt < 8; ++nt) {
            const int r = warp_m + mt * 16 + gid;
            const int col = warp_n + nt * 8 + tig * 2;
            *reinterpret_cast<float2*>(outS + r * OPAD + col) =
                make_float2(acc[mt][nt][0], acc[mt][nt][1]);
            *reinterpret_cast<float2*>(outS + (r + 8) * OPAD + col) =
                make_float2(acc[mt][nt][2], acc[mt][nt][3]);
        }
    }
    __syncthreads();

    // --- per-row epilogue: softmax gates, expert mix, sigmoid heads ---
    if (tid < TILE_M) {
        const float* rowv = outS + tid * OPAD;

        float g[2][10];
        #pragma unroll
        for (int t = 0; t < 2; ++t) {
            float s = 0.0f;
            #pragma unroll
            for (int e = 0; e < 10; ++e) {
                float l = rowv[100 + t * 10 + e] + gate_b[t * 10 + e];
                float ex = expf(l);
                g[t][e] = ex; s += ex;
            }
            float inv = 1.0f / s;
            #pragma unroll
            for (int e = 0; e < 10; ++e) g[t][e] *= inv;
        }

        float ti0[10], ti1[10];
        #pragma unroll
        for (int u = 0; u < 10; ++u) { ti0[u] = 0.0f; ti1[u] = 0.0f; }
        #pragma unroll
        for (int e = 0; e < 10; ++e) {
            const float g0 = g[0][e], g1 = g[1][e];
            #pragma unroll
            for (int u = 0; u < 10; ++u) {
                const int j = e * 10 + u;
                float v = fmaxf(rowv[j] + expert_b[j], 0.0f);
                ti0[u] += v * g0;
                ti1[u] += v * g1;
            }
        }

        float zc = ctr_b[0], zv = cvr_b[0];
        #pragma unroll
        for (int u = 0; u < 10; ++u) {
            zc += ti0[u] * ctr_w[u];
            zv += ti1[u] * cvr_w[u];
        }
        const int gr = row0 + tid;
        out[gr]         = 1.0f / (1.0f + expf(-zc));
        out[BROWS + gr] = 1.0f / (1.0f + expf(-zv));
    }
}

// ---------------- launch ----------------
extern "C" void kernel_launch(void* const* d_in, const int* in_sizes, int n_in,
                              void* d_out, int out_size) {
    const float* x        = (const float*)d_in[0];
    const float* expert_w = (const float*)d_in[3];
    const float* expert_b = (const float*)d_in[4];
    const float* gate_w   = (const float*)d_in[5];
    const float* gate_b   = (const float*)d_in[6];
    const float* ctr_w    = (const float*)d_in[7];
    const float* ctr_b    = (const float*)d_in[8];
    const float* cvr_w    = (const float*)d_in[9];
    const float* cvr_b    = (const float*)d_in[10];
    float* out = (float*)d_out;

    cudaFuncSetAttribute(mmoe_main_kernel,
                         cudaFuncAttributeMaxDynamicSharedMemorySize, SMEM_BYTES);

    pack_weights_kernel<<<dim3(12, 4), 256>>>(expert_w, gate_w);
    mmoe_main_kernel<<<BROWS / TILE_M, 256, SMEM_BYTES>>>(
        x, expert_b, gate_b, ctr_w, ctr_b, cvr_w, cvr_b, out);
}